// round 15
// baseline (speedup 1.0000x reference)
#include <cuda_runtime.h>
#include <cuda_bf16.h>
#include <cstdint>

#define BATCH   8192
#define DIM     1024
#define NCLASS  1000
#define CPAD    1024
#define N_PAIRS 499500.0f   // 1000*999/2

// ---------------- scratch (device globals; zero at load) ----------------
__device__ int   g_lab64;                             // set by k_update block 0
__device__ float g_centers_new[CPAD * DIM];           // rows >= NCLASS stay 0
__device__ __nv_bfloat16 g_centers_bf16[CPAD * DIM];  // rows >= NCLASS stay 0
__device__ float g_sq[CPAD];                          // entries >= NCLASS stay 0
__device__ float g_accum[2];                          // zeroed by k_fused final block
__device__ int   g_done;                              // zeroed by k_fused final block

// ---------------- helpers ----------------
__device__ __forceinline__ int decode_label(const int* w, int b, int lab64) {
    int v = lab64 ? w[2 * b] : w[b];
    return (v >= 0 && v < NCLASS) ? v : 0;
}

__device__ __forceinline__ float warp_sum(float v) {
    #pragma unroll
    for (int o = 16; o; o >>= 1) v += __shfl_xor_sync(0xffffffffu, v, o);
    return v;
}

__device__ __forceinline__ void ldsm_x4(uint32_t r[4], uint32_t saddr) {
    asm volatile("ldmatrix.sync.aligned.m8n8.x4.shared.b16 {%0,%1,%2,%3}, [%4];"
                 : "=r"(r[0]), "=r"(r[1]), "=r"(r[2]), "=r"(r[3]) : "r"(saddr));
}

__device__ __forceinline__ void mma16816(float d[4], const uint32_t a[4], uint32_t b0, uint32_t b1) {
    asm volatile("mma.sync.aligned.m16n8k16.row.col.f32.bf16.bf16.f32 "
                 "{%0,%1,%2,%3},{%4,%5,%6,%7},{%8,%9},{%0,%1,%2,%3};"
                 : "+f"(d[0]), "+f"(d[1]), "+f"(d[2]), "+f"(d[3])
                 : "r"(a[0]), "r"(a[1]), "r"(a[2]), "r"(a[3]), "r"(b0), "r"(b1));
}

// ============ 1: center update — self-contained member scan, no prep kernel ============
__global__ __launch_bounds__(256) void k_update(const float* __restrict__ f,
                                                const float* __restrict__ centers,
                                                const void* __restrict__ labels) {
    __shared__ float s_acc[DIM];       // 4 KB class accumulator
    __shared__ int   s_mem[BATCH];     // 32 KB member list (handles any distribution)
    __shared__ int   s_cnt;
    __shared__ int   s_lab64;
    __shared__ float red[8];

    int c = blockIdx.x;
    int t = threadIdx.x;
    int wid = t >> 5, lane = t & 31;
    const int* w = (const int*)labels;

    // label width probe (warp 0)
    if (t < 32) {
        unsigned nz = __ballot_sync(0xffffffffu, w[2 * t + 1] != 0);
        if (t == 0) {
            s_lab64 = (nz == 0u);
            if (c == 0) g_lab64 = s_lab64;   // published for k_fused
        }
    }
    if (t == 0) s_cnt = 0;
    *(float4*)&s_acc[t * 4] = make_float4(0.f, 0.f, 0.f, 0.f);
    __syncthreads();
    int lab64 = s_lab64;

    // scan all labels (L1/L2-hot, 32 loads/thread), compact members of class c
    #pragma unroll 4
    for (int q = 0; q < BATCH / 256; q++) {
        int b = q * 256 + t;
        if (decode_label(w, b, lab64) == c) {
            int p = atomicAdd(&s_cnt, 1);
            s_mem[p] = b;
        }
    }
    __syncthreads();
    int cnt = s_cnt;

    // warp-per-member-row: inline norm + smem-atomic accumulate
    for (int i = wid; i < cnt; i += 8) {
        int r = s_mem[i];
        const float4* row = (const float4*)(f + (size_t)r * DIM);
        float4 v[8];
        float ss = 0.f;
        #pragma unroll
        for (int q = 0; q < 8; q++) {
            v[q] = row[q * 32 + lane];
            ss += v[q].x * v[q].x + v[q].y * v[q].y + v[q].z * v[q].z + v[q].w * v[q].w;
        }
        ss = warp_sum(ss);
        float inv = 1.0f / fmaxf(sqrtf(ss), 1e-12f);
        #pragma unroll
        for (int q = 0; q < 8; q++) {
            float* dst = &s_acc[q * 128 + lane * 4];   // conflict-free across lanes
            atomicAdd(dst + 0, v[q].x * inv);
            atomicAdd(dst + 1, v[q].y * inv);
            atomicAdd(dst + 2, v[q].z * inv);
            atomicAdd(dst + 3, v[q].w * inv);
        }
    }
    __syncthreads();

    float4 sum = *(float4*)&s_acc[t * 4];
    float rc = 1.0f / fmaxf((float)cnt, 1.0f);
    float4 mean = {sum.x * rc, sum.y * rc, sum.z * rc, sum.w * rc};
    float4 co = *(const float4*)(centers + (size_t)c * DIM + t * 4);

    int zflag = (co.x == 0.f && co.y == 0.f && co.z == 0.f && co.w == 0.f);
    int allz = __syncthreads_and(zflag);

    float4 outv;
    if (cnt > 0) {
        if (allz) outv = mean;
        else {
            outv.x = 0.9f * co.x + 0.1f * mean.x;
            outv.y = 0.9f * co.y + 0.1f * mean.y;
            outv.z = 0.9f * co.z + 0.1f * mean.z;
            outv.w = 0.9f * co.w + 0.1f * mean.w;
        }
    } else outv = co;

    *(float4*)(g_centers_new + (size_t)c * DIM + t * 4) = outv;

    __nv_bfloat162 p0 = __floats2bfloat162_rn(outv.x, outv.y);
    __nv_bfloat162 p1 = __floats2bfloat162_rn(outv.z, outv.w);
    uint2 pk;
    pk.x = *(uint32_t*)&p0;
    pk.y = *(uint32_t*)&p1;
    *(uint2*)(g_centers_bf16 + (size_t)c * DIM + t * 4) = pk;

    float s = outv.x * outv.x + outv.y * outv.y + outv.z * outv.z + outv.w * outv.w;
    s = warp_sum(s);
    if ((t & 31) == 0) red[t >> 5] = s;
    __syncthreads();
    if (t == 0) {
        float tot = 0.f;
        #pragma unroll
        for (int q = 0; q < 8; q++) tot += red[q];
        g_sq[c] = tot;
    }
}

// ============ 2: fused GEMM(64x64 tiles) + intra(f/fa-split) + final/reset (R14 body) ============
#define GEMM_BLOCKS  136            // 16*17/2 upper-tri 64x64 tiles
#define INTRA_BLOCKS 2048           // 1024 f-blocks + 1024 fa-blocks (interleaved)
#define KTILE 64
#define RSTRIDE 144                 // 64 bf16 = 128 B + 16 B pad
#define GEMM_SMEM (128 * RSTRIDE)   // A(64 rows) + B(64 rows): 18432 B

__global__ __launch_bounds__(256, 4) void k_fused(const float* __restrict__ f,
                                                  const float* __restrict__ fa,
                                                  const void* __restrict__ labels,
                                                  float* __restrict__ out) {
    __shared__ __align__(16) char s_raw[GEMM_SMEM];
    __shared__ int s_amlast;

    int t = threadIdx.x;
    int wid = t >> 5, lane = t & 31;

    if (blockIdx.x >= GEMM_BLOCKS) {
        // -------- intra: one warp = one row of f OR fa --------
        int ib = blockIdx.x - GEMM_BLOCKS;
        int half = ib & 1;                 // 0: f, 1: fa
        int b = (ib >> 1) * 8 + wid;
        int lab64 = g_lab64;
        int lab = decode_label((const int*)labels, b, lab64);

        const float* src = half ? fa : f;
        const float4* fr = (const float4*)(src + (size_t)b * DIM);
        const float4* cr = (const float4*)(g_centers_new + (size_t)lab * DIM);

        float4 v[8];
        #pragma unroll
        for (int q = 0; q < 8; q++) v[q] = fr[q * 32 + lane];

        float dot = 0.f, ss = 0.f;
        #pragma unroll
        for (int q = 0; q < 8; q++) {
            float4 cv = cr[q * 32 + lane];
            dot += v[q].x * cv.x + v[q].y * cv.y + v[q].z * cv.z + v[q].w * cv.w;
            ss  += v[q].x * v[q].x + v[q].y * v[q].y + v[q].z * v[q].z + v[q].w * v[q].w;
        }
        dot = warp_sum(dot);
        ss  = warp_sum(ss);

        float* bsum = (float*)s_raw;
        if (t == 0) *bsum = 0.f;
        __syncthreads();
        if (lane == 0) {
            float inv = 1.0f / fmaxf(sqrtf(ss), 1e-12f);
            float sqc = g_sq[lab];
            float d = sqrtf(fmaxf(1.0f - 2.0f * dot * inv + sqc, 0.0f));
            atomicAdd(bsum, d);
        }
        __syncthreads();
        if (t == 0) atomicAdd(&g_accum[0], *bsum);
    } else {
        // -------- bf16 GEMM, 64x64 tile, K-tile 64, register staging --------
        int rem = blockIdx.x, ti = 0;
        while (rem >= 16 - ti) { rem -= 16 - ti; ti++; }
        int tj = ti + rem;
        int ibase = ti * 64, jbase = tj * 64;

        // 8 warps: 4 x 2 grid of 16x32 warp tiles
        int m0 = (wid & 3) * 16;
        int n0 = (wid >> 2) * 32;

        uint32_t sbase = (uint32_t)__cvta_generic_to_shared(s_raw);

        int goff[4], soff[4];
        #pragma unroll
        for (int s = 0; s < 4; s++) {
            int slot = t + s * 256;
            int row = slot >> 3, c16 = slot & 7;
            int grow = (row < 64) ? (ibase + row) : (jbase + row - 64);
            goff[s] = grow * DIM + c16 * 8;       // bf16 elements
            soff[s] = row * RSTRIDE + c16 * 16;   // bytes
        }

        #pragma unroll
        for (int s = 0; s < 4; s++) {
            uint4 val = *(const uint4*)(g_centers_bf16 + goff[s]);
            *(uint4*)(s_raw + soff[s]) = val;
        }
        __syncthreads();

        float acc[4][4] = {};
        int lr = lane & 15, lc = lane >> 4;
        uint32_t abase0 = sbase + (m0 + lr) * RSTRIDE + lc * 16;
        uint32_t bbase0 = sbase + (64 + n0 + lr) * RSTRIDE + lc * 16;

        for (int it = 0; it < 16; it++) {
            uint4 stg[4];
            if (it < 15) {
                #pragma unroll
                for (int s = 0; s < 4; s++)
                    stg[s] = *(const uint4*)(g_centers_bf16 + goff[s] + (it + 1) * KTILE);
            }

            #pragma unroll
            for (int kk = 0; kk < 4; kk++) {
                uint32_t af[4], bf[2][4];
                ldsm_x4(af, abase0 + kk * 32);
                ldsm_x4(bf[0], bbase0 + kk * 32);
                ldsm_x4(bf[1], bbase0 + kk * 32 + 16 * RSTRIDE);

                #pragma unroll
                for (int g = 0; g < 2; g++) {
                    mma16816(acc[g * 2 + 0], af, bf[g][0], bf[g][2]);
                    mma16816(acc[g * 2 + 1], af, bf[g][1], bf[g][3]);
                }
            }
            __syncthreads();
            if (it < 15) {
                #pragma unroll
                for (int s = 0; s < 4; s++)
                    *(uint4*)(s_raw + soff[s]) = stg[s];
            }
            __syncthreads();
        }

        // epilogue: dist + relu reduction
        float local = 0.f;
        int g8 = lane >> 2, tg = lane & 3;
        #pragma unroll
        for (int nt = 0; nt < 4; nt++) {
            #pragma unroll
            for (int r = 0; r < 4; r++) {
                int i = ibase + m0 + g8 + ((r >> 1) * 8);
                int j = jbase + n0 + nt * 8 + tg * 2 + (r & 1);
                if (i < j && j < NCLASS) {
                    float d2 = g_sq[i] + g_sq[j] - 2.0f * acc[nt][r];
                    float d  = sqrtf(fmaxf(d2, 0.0f));
                    local += fmaxf(1.0f - d, 0.0f);
                }
            }
        }
        local = warp_sum(local);
        float* ws = (float*)s_raw;
        __syncthreads();
        if (lane == 0) ws[wid] = local;
        __syncthreads();
        if (t == 0) {
            float tot = 0.f;
            #pragma unroll
            for (int q = 0; q < 8; q++) tot += ws[q];
            atomicAdd(&g_accum[1], tot);
        }
    }

    // -------- last-block final output + state reset for next replay --------
    __threadfence();
    __syncthreads();
    if (t == 0) {
        int d = atomicAdd(&g_done, 1);
        s_amlast = (d == (int)gridDim.x - 1);
    }
    __syncthreads();
    if (s_amlast && t == 0) {
        float intra = g_accum[0] / (float)BATCH;
        float inter = g_accum[1] / N_PAIRS;
        out[0] = intra - 0.5f * inter;
        g_accum[0] = 0.f;
        g_accum[1] = 0.f;
        g_done = 0;
    }
}

// ---------------- launch ----------------
extern "C" void kernel_launch(void* const* d_in, const int* in_sizes, int n_in,
                              void* d_out, int out_size) {
    const float* f       = (const float*)d_in[0];
    const float* fa      = (const float*)d_in[1];
    const float* centers = (const float*)d_in[2];
    const void*  labels  = d_in[3];
    float* out = (float*)d_out;

    k_update<<<NCLASS, 256>>>(f, centers, labels);
    k_fused<<<GEMM_BLOCKS + INTRA_BLOCKS, 256>>>(f, fa, labels, out);
}

// round 16
// speedup vs baseline: 1.0132x; 1.0132x over previous
#include <cuda_runtime.h>
#include <cuda_bf16.h>
#include <cstdint>

#define BATCH   8192
#define DIM     1024
#define NCLASS  1000
#define CPAD    1024
#define N_PAIRS 499500.0f   // 1000*999/2

// ---------------- scratch (device globals; zero at load) ----------------
__device__ int   g_lab64;                             // set by k_update block 0
__device__ float g_centers_new[CPAD * DIM];           // rows >= NCLASS stay 0
__device__ __nv_bfloat16 g_centers_bf16[CPAD * DIM];  // rows >= NCLASS stay 0
__device__ float g_sq[CPAD];                          // entries >= NCLASS stay 0
__device__ float g_accum[2];                          // zeroed by k_fused final block
__device__ int   g_done;                              // zeroed by k_fused final block

// ---------------- helpers ----------------
__device__ __forceinline__ int decode_label(const int* w, int b, int lab64) {
    int v = lab64 ? w[2 * b] : w[b];
    return (v >= 0 && v < NCLASS) ? v : 0;
}

__device__ __forceinline__ float warp_sum(float v) {
    #pragma unroll
    for (int o = 16; o; o >>= 1) v += __shfl_xor_sync(0xffffffffu, v, o);
    return v;
}

__device__ __forceinline__ void ldsm_x4(uint32_t r[4], uint32_t saddr) {
    asm volatile("ldmatrix.sync.aligned.m8n8.x4.shared.b16 {%0,%1,%2,%3}, [%4];"
                 : "=r"(r[0]), "=r"(r[1]), "=r"(r[2]), "=r"(r[3]) : "r"(saddr));
}

__device__ __forceinline__ void mma16816(float d[4], const uint32_t a[4], uint32_t b0, uint32_t b1) {
    asm volatile("mma.sync.aligned.m16n8k16.row.col.f32.bf16.bf16.f32 "
                 "{%0,%1,%2,%3},{%4,%5,%6,%7},{%8,%9},{%0,%1,%2,%3};"
                 : "+f"(d[0]), "+f"(d[1]), "+f"(d[2]), "+f"(d[3])
                 : "r"(a[0]), "r"(a[1]), "r"(a[2]), "r"(a[3]), "r"(b0), "r"(b1));
}

// ============ 1: center update — register-batched label scan, ushort member list ============
__global__ __launch_bounds__(256) void k_update(const float* __restrict__ f,
                                                const float* __restrict__ centers,
                                                const void* __restrict__ labels) {
    __shared__ float s_acc[DIM];                 // 4 KB class accumulator
    __shared__ unsigned short s_mem[BATCH];      // 16 KB member list
    __shared__ int   s_cnt;
    __shared__ int   s_lab64;
    __shared__ float red[8];

    int c = blockIdx.x;
    int t = threadIdx.x;
    int wid = t >> 5, lane = t & 31;
    const int* w = (const int*)labels;

    if (t < 32) {
        unsigned nz = __ballot_sync(0xffffffffu, w[2 * t + 1] != 0);
        if (t == 0) {
            s_lab64 = (nz == 0u);
            if (c == 0) g_lab64 = s_lab64;   // published for k_fused
        }
    }
    if (t == 0) s_cnt = 0;
    *(float4*)&s_acc[t * 4] = make_float4(0.f, 0.f, 0.f, 0.f);
    __syncthreads();
    int lab64 = s_lab64;
    int stride = lab64 ? 2 : 1;

    // register-batched label scan (MLP 8 per chunk), compact members of class c
    #pragma unroll
    for (int ch = 0; ch < 4; ch++) {
        int lv[8];
        #pragma unroll
        for (int q = 0; q < 8; q++)
            lv[q] = w[(ch * 2048 + q * 256 + t) * stride];
        #pragma unroll
        for (int q = 0; q < 8; q++) {
            int v = lv[q];
            v = (v >= 0 && v < NCLASS) ? v : 0;
            if (v == c) {
                int p = atomicAdd(&s_cnt, 1);
                if (p < BATCH) s_mem[p] = (unsigned short)(ch * 2048 + q * 256 + t);
            }
        }
    }
    __syncthreads();
    int cnt = s_cnt;

    // warp-per-member-row: inline norm + smem-atomic accumulate
    for (int i = wid; i < cnt; i += 8) {
        int r = s_mem[i];
        const float4* row = (const float4*)(f + (size_t)r * DIM);
        float4 v[8];
        float ss = 0.f;
        #pragma unroll
        for (int q = 0; q < 8; q++) {
            v[q] = row[q * 32 + lane];
            ss += v[q].x * v[q].x + v[q].y * v[q].y + v[q].z * v[q].z + v[q].w * v[q].w;
        }
        ss = warp_sum(ss);
        float inv = 1.0f / fmaxf(sqrtf(ss), 1e-12f);
        #pragma unroll
        for (int q = 0; q < 8; q++) {
            float* dst = &s_acc[q * 128 + lane * 4];   // conflict-free across lanes
            atomicAdd(dst + 0, v[q].x * inv);
            atomicAdd(dst + 1, v[q].y * inv);
            atomicAdd(dst + 2, v[q].z * inv);
            atomicAdd(dst + 3, v[q].w * inv);
        }
    }
    __syncthreads();

    float4 sum = *(float4*)&s_acc[t * 4];
    float rc = 1.0f / fmaxf((float)cnt, 1.0f);
    float4 mean = {sum.x * rc, sum.y * rc, sum.z * rc, sum.w * rc};
    float4 co = *(const float4*)(centers + (size_t)c * DIM + t * 4);

    int zflag = (co.x == 0.f && co.y == 0.f && co.z == 0.f && co.w == 0.f);
    int allz = __syncthreads_and(zflag);

    float4 outv;
    if (cnt > 0) {
        if (allz) outv = mean;
        else {
            outv.x = 0.9f * co.x + 0.1f * mean.x;
            outv.y = 0.9f * co.y + 0.1f * mean.y;
            outv.z = 0.9f * co.z + 0.1f * mean.z;
            outv.w = 0.9f * co.w + 0.1f * mean.w;
        }
    } else outv = co;

    *(float4*)(g_centers_new + (size_t)c * DIM + t * 4) = outv;

    __nv_bfloat162 p0 = __floats2bfloat162_rn(outv.x, outv.y);
    __nv_bfloat162 p1 = __floats2bfloat162_rn(outv.z, outv.w);
    uint2 pk;
    pk.x = *(uint32_t*)&p0;
    pk.y = *(uint32_t*)&p1;
    *(uint2*)(g_centers_bf16 + (size_t)c * DIM + t * 4) = pk;

    float s = outv.x * outv.x + outv.y * outv.y + outv.z * outv.z + outv.w * outv.w;
    s = warp_sum(s);
    if ((t & 31) == 0) red[t >> 5] = s;
    __syncthreads();
    if (t == 0) {
        float tot = 0.f;
        #pragma unroll
        for (int q = 0; q < 8; q++) tot += red[q];
        g_sq[c] = tot;
    }
}

// ============ 2: fused GEMM(64x64) + intra(bf16 centers, streaming loads) + final ============
#define GEMM_BLOCKS  136            // 16*17/2 upper-tri 64x64 tiles
#define INTRA_BLOCKS 2048           // 1024 f-blocks + 1024 fa-blocks (interleaved)
#define KTILE 64
#define RSTRIDE 144                 // 64 bf16 = 128 B + 16 B pad
#define GEMM_SMEM (128 * RSTRIDE)   // A(64 rows) + B(64 rows): 18432 B

__global__ __launch_bounds__(256, 4) void k_fused(const float* __restrict__ f,
                                                  const float* __restrict__ fa,
                                                  const void* __restrict__ labels,
                                                  float* __restrict__ out) {
    __shared__ __align__(16) char s_raw[GEMM_SMEM];
    __shared__ int s_amlast;

    int t = threadIdx.x;
    int wid = t >> 5, lane = t & 31;

    if (blockIdx.x >= GEMM_BLOCKS) {
        // -------- intra: one warp = one row of f OR fa; centers read as bf16 --------
        int ib = blockIdx.x - GEMM_BLOCKS;
        int half = ib & 1;                 // 0: f, 1: fa
        int b = (ib >> 1) * 8 + wid;
        int lab64 = g_lab64;
        int lab = decode_label((const int*)labels, b, lab64);

        const float* src = half ? fa : f;
        const float4* fr = (const float4*)(src + (size_t)b * DIM);
        const uint2*  cr = (const uint2*)(g_centers_bf16 + (size_t)lab * DIM);

        float4 v[8];
        #pragma unroll
        for (int q = 0; q < 8; q++) v[q] = __ldcs(&fr[q * 32 + lane]);   // streaming

        float dot = 0.f, ss = 0.f;
        #pragma unroll
        for (int q = 0; q < 8; q++) {
            uint2 cb = cr[q * 32 + lane];    // 4 bf16 center values (8 B)
            float2 c01 = __bfloat1622float2(*(const __nv_bfloat162*)&cb.x);
            float2 c23 = __bfloat1622float2(*(const __nv_bfloat162*)&cb.y);
            dot += v[q].x * c01.x + v[q].y * c01.y + v[q].z * c23.x + v[q].w * c23.y;
            ss  += v[q].x * v[q].x + v[q].y * v[q].y + v[q].z * v[q].z + v[q].w * v[q].w;
        }
        dot = warp_sum(dot);
        ss  = warp_sum(ss);

        float* bsum = (float*)s_raw;
        if (t == 0) *bsum = 0.f;
        __syncthreads();
        if (lane == 0) {
            float inv = 1.0f / fmaxf(sqrtf(ss), 1e-12f);
            float sqc = g_sq[lab];
            float d = sqrtf(fmaxf(1.0f - 2.0f * dot * inv + sqc, 0.0f));
            atomicAdd(bsum, d);
        }
        __syncthreads();
        if (t == 0) atomicAdd(&g_accum[0], *bsum);
    } else {
        // -------- bf16 GEMM, 64x64 tile, K-tile 64, register staging (measured-best) --------
        int rem = blockIdx.x, ti = 0;
        while (rem >= 16 - ti) { rem -= 16 - ti; ti++; }
        int tj = ti + rem;
        int ibase = ti * 64, jbase = tj * 64;

        int m0 = (wid & 3) * 16;
        int n0 = (wid >> 2) * 32;

        uint32_t sbase = (uint32_t)__cvta_generic_to_shared(s_raw);

        int goff[4], soff[4];
        #pragma unroll
        for (int s = 0; s < 4; s++) {
            int slot = t + s * 256;
            int row = slot >> 3, c16 = slot & 7;
            int grow = (row < 64) ? (ibase + row) : (jbase + row - 64);
            goff[s] = grow * DIM + c16 * 8;       // bf16 elements
            soff[s] = row * RSTRIDE + c16 * 16;   // bytes
        }

        #pragma unroll
        for (int s = 0; s < 4; s++) {
            uint4 val = *(const uint4*)(g_centers_bf16 + goff[s]);
            *(uint4*)(s_raw + soff[s]) = val;
        }
        __syncthreads();

        float acc[4][4] = {};
        int lr = lane & 15, lc = lane >> 4;
        uint32_t abase0 = sbase + (m0 + lr) * RSTRIDE + lc * 16;
        uint32_t bbase0 = sbase + (64 + n0 + lr) * RSTRIDE + lc * 16;

        for (int it = 0; it < 16; it++) {
            uint4 stg[4];
            if (it < 15) {
                #pragma unroll
                for (int s = 0; s < 4; s++)
                    stg[s] = *(const uint4*)(g_centers_bf16 + goff[s] + (it + 1) * KTILE);
            }

            #pragma unroll
            for (int kk = 0; kk < 4; kk++) {
                uint32_t af[4], bf[2][4];
                ldsm_x4(af, abase0 + kk * 32);
                ldsm_x4(bf[0], bbase0 + kk * 32);
                ldsm_x4(bf[1], bbase0 + kk * 32 + 16 * RSTRIDE);

                #pragma unroll
                for (int g = 0; g < 2; g++) {
                    mma16816(acc[g * 2 + 0], af, bf[g][0], bf[g][2]);
                    mma16816(acc[g * 2 + 1], af, bf[g][1], bf[g][3]);
                }
            }
            __syncthreads();
            if (it < 15) {
                #pragma unroll
                for (int s = 0; s < 4; s++)
                    *(uint4*)(s_raw + soff[s]) = stg[s];
            }
            __syncthreads();
        }

        // epilogue: dist + relu reduction
        float local = 0.f;
        int g8 = lane >> 2, tg = lane & 3;
        #pragma unroll
        for (int nt = 0; nt < 4; nt++) {
            #pragma unroll
            for (int r = 0; r < 4; r++) {
                int i = ibase + m0 + g8 + ((r >> 1) * 8);
                int j = jbase + n0 + nt * 8 + tg * 2 + (r & 1);
                if (i < j && j < NCLASS) {
                    float d2 = g_sq[i] + g_sq[j] - 2.0f * acc[nt][r];
                    float d  = sqrtf(fmaxf(d2, 0.0f));
                    local += fmaxf(1.0f - d, 0.0f);
                }
            }
        }
        local = warp_sum(local);
        float* ws = (float*)s_raw;
        __syncthreads();
        if (lane == 0) ws[wid] = local;
        __syncthreads();
        if (t == 0) {
            float tot = 0.f;
            #pragma unroll
            for (int q = 0; q < 8; q++) tot += ws[q];
            atomicAdd(&g_accum[1], tot);
        }
    }

    // -------- last-block final output + state reset for next replay --------
    __threadfence();
    __syncthreads();
    if (t == 0) {
        int d = atomicAdd(&g_done, 1);
        s_amlast = (d == (int)gridDim.x - 1);
    }
    __syncthreads();
    if (s_amlast && t == 0) {
        float intra = g_accum[0] / (float)BATCH;
        float inter = g_accum[1] / N_PAIRS;
        out[0] = intra - 0.5f * inter;
        g_accum[0] = 0.f;
        g_accum[1] = 0.f;
        g_done = 0;
    }
}

// ---------------- launch ----------------
extern "C" void kernel_launch(void* const* d_in, const int* in_sizes, int n_in,
                              void* d_out, int out_size) {
    const float* f       = (const float*)d_in[0];
    const float* fa      = (const float*)d_in[1];
    const float* centers = (const float*)d_in[2];
    const void*  labels  = d_in[3];
    float* out = (float*)d_out;

    k_update<<<NCLASS, 256>>>(f, centers, labels);
    k_fused<<<GEMM_BLOCKS + INTRA_BLOCKS, 256>>>(f, fa, labels, out);
}